// round 1
// baseline (speedup 1.0000x reference)
#include <cuda_runtime.h>
#include <cstddef>

// Adaptive separable convolution (SepConv)
// out[b,c,h,w] = sum_i sum_j inp[b,c,h+i,w+j] * V[b,i,h,w] * Hz[b,j,h,w]
//
// Strategy: each thread computes 2 adjacent output pixels (w0 even, w0+1) for
// all 3 channels (channel loop outer, one channel patch in smem at a time).
// Per-pixel horizontal weights live in registers (fully unrolled static
// indexing). Inner loop reads the input row from shared memory as float2
// (lane stride 8B -> conflict-free LDS.64); each 8B load feeds 4 FFMAs.

#define KF 51
#define BB 2
#define CC 3
#define HH 256
#define WW 256
#define IN_H (HH + KF - 1)   // 306
#define IN_W (WW + KF - 1)   // 306

#define TILE_W 64
#define TILE_H 4
#define PATCH_H (TILE_H + KF - 1)   // 54
#define PATCH_W (TILE_W + KF - 1)   // 114
#define PATCH_WP 116                // padded, even (8B row alignment)

#define NTHREADS 128                // 4 warps, one output row per warp

__global__ void __launch_bounds__(NTHREADS)
sepconv_kernel(const float* __restrict__ inp,
               const float* __restrict__ ver,
               const float* __restrict__ hor,
               float* __restrict__ out)
{
    __shared__ __align__(16) float sm[PATCH_H][PATCH_WP];

    const int bx = blockIdx.x;            // 0..3   tile col
    const int by = blockIdx.y;            // 0..63  tile row
    const int b  = blockIdx.z;            // batch
    const int x0 = bx * TILE_W;
    const int y0 = by * TILE_H;

    const int tid  = threadIdx.x;
    const int lane = tid & 31;
    const int wy   = tid >> 5;            // warp id == row within tile
    const int y    = y0 + wy;             // output row
    const int w0   = x0 + 2 * lane;       // even output col (pixel pair w0, w0+1)

    // ---- preload per-pixel horizontal weights into registers ----
    // h0[u] weights pixel w0 at window offset u (j = u),      h0[51] = 0 pad
    // h1[u] weights pixel w0+1 at offset u      (j = u - 1),  h1[0]  = 0 pad
    float h0[KF + 1];
    float h1[KF + 1];
    {
        const float* Hb = hor + ((size_t)b * KF * HH * WW) + (size_t)y * WW + w0;
        h0[KF] = 0.0f;
        h1[0]  = 0.0f;
#pragma unroll
        for (int j = 0; j < KF; ++j) {
            float2 t = *(const float2*)(Hb + (size_t)j * (HH * WW));
            h0[j]     = t.x;
            h1[j + 1] = t.y;
        }
    }

    const float* Vb = ver + ((size_t)b * KF * HH * WW) + (size_t)y * WW + w0;

    for (int c = 0; c < CC; ++c) {
        // ---- fill single-channel input patch ----
        __syncthreads();   // previous channel's compute must finish before refill
        {
            const float* src = inp + ((size_t)(b * CC + c) * IN_H + y0) * IN_W + x0;
            for (int idx = tid; idx < PATCH_H * PATCH_W; idx += NTHREADS) {
                int r  = idx / PATCH_W;
                int cc = idx - r * PATCH_W;
                sm[r][cc] = src[(size_t)r * IN_W + cc];
            }
        }
        __syncthreads();

        // ---- compute 2 output pixels ----
        float acc0 = 0.0f, acc1 = 0.0f;

        for (int i = 0; i < KF; ++i) {
            float2 v = *(const float2*)(Vb + (size_t)i * (HH * WW));

            const float* srow = &sm[wy + i][2 * lane];

            // split rs accumulators to shorten FFMA RAW chains
            float rs0a = 0.0f, rs0b = 0.0f;
            float rs1a = 0.0f, rs1b = 0.0f;

#pragma unroll
            for (int k = 0; k < 26; ++k) {       // u = 2k, 2k+1 in [0, 51]
                float2 s = *(const float2*)(srow + 2 * k);
                rs0a = fmaf(h0[2 * k],     s.x, rs0a);
                rs0b = fmaf(h0[2 * k + 1], s.y, rs0b);
                rs1a = fmaf(h1[2 * k],     s.x, rs1a);
                rs1b = fmaf(h1[2 * k + 1], s.y, rs1b);
            }

            acc0 = fmaf(v.x, rs0a + rs0b, acc0);
            acc1 = fmaf(v.y, rs1a + rs1b, acc1);
        }

        float* o = out + ((size_t)(b * CC + c) * HH + y) * WW + w0;
        *(float2*)o = make_float2(acc0, acc1);
    }
}

extern "C" void kernel_launch(void* const* d_in, const int* in_sizes, int n_in,
                              void* d_out, int out_size)
{
    (void)in_sizes; (void)n_in; (void)out_size;
    const float* inp = (const float*)d_in[0];   // [B, C, 306, 306]
    const float* ver = (const float*)d_in[1];   // [B, 51, 256, 256]
    const float* hor = (const float*)d_in[2];   // [B, 51, 256, 256]
    float*       out = (float*)d_out;           // [B, C, 256, 256]

    dim3 grid(WW / TILE_W, HH / TILE_H, BB);    // (4, 64, 2) = 512 blocks
    dim3 block(NTHREADS);
    sepconv_kernel<<<grid, block>>>(inp, ver, hor, out);
}